// round 12
// baseline (speedup 1.0000x reference)
#include <cuda_runtime.h>
#include <cstdint>

#define TT   28
#define IND  28
#define HID  64
#define EE   16
#define ES   20        // padded operand row stride (floats)
#define OUTD 10
#define NT   256
#define K0   92        // layer0 K (28 x + 64 h)
#define K0H  46        // layer0 K-half
#define K1H  64        // layer1 K-half
#define HSZ  (HID*ES)  // one hs buffer

// Shared memory (floats):
//  h1seq [TT][HID][ES]      = 35840
//  zbuf  [92][ES]           =  1840   (x rows 0..27, h0 rows 28..91)
//  hs    [2][HID][ES]       =  2560   (layer1 h2 state, parity buffers)
//  xch   [2] x ulonglong2[8*128] = 8192 floats (parity buffers)
//  actx  [64][36]           =  2304
//  wlin 640, blin 16
#define OFF_H1SEQ 0
#define OFF_ZBUF  (OFF_H1SEQ + TT*HID*ES)
#define OFF_HS    (OFF_ZBUF + K0*ES)
#define OFF_XCH   (OFF_HS + 2*HSZ)
#define OFF_ACTX  (OFF_XCH + 2*8*128*4)
#define OFF_WLIN  (OFF_ACTX + 64*36)
#define OFF_BLIN  (OFF_WLIN + OUTD*HID)
#define SMEM_FLOATS (OFF_BLIN + 16)
#define SMEM_BYTES  (SMEM_FLOATS * 4)

typedef unsigned long long u64;

__device__ __forceinline__ u64 splat2(float w) {
    u64 r; asm("mov.b64 %0, {%1, %1};" : "=l"(r) : "f"(w)); return r;
}
__device__ __forceinline__ void ffma2(u64& d, u64 a, u64 b) {
    asm("fma.rn.f32x2 %0, %1, %2, %0;" : "+l"(d) : "l"(a), "l"(b));
}
__device__ __forceinline__ void fadd2(u64& d, u64 a) {
    asm("add.rn.f32x2 %0, %1, %0;" : "+l"(d) : "l"(a));
}
__device__ __forceinline__ float2 unpack2(u64 v) {
    float2 f; asm("mov.b64 {%0, %1}, %2;" : "=f"(f.x), "=f"(f.y) : "l"(v)); return f;
}
__device__ __forceinline__ float tanhfast(float x) {
    float r; asm("tanh.approx.f32 %0, %1;" : "=f"(r) : "f"(x)); return r;
}
__device__ __forceinline__ float sigfast(float x) {
    return fmaf(0.5f, tanhfast(0.5f * x), 0.5f);
}
__device__ __forceinline__ void bar_sync_n(int id, int n) {
    asm volatile("bar.sync %0, %1;" :: "r"(id), "r"(n) : "memory");
}
__device__ __forceinline__ void bar_arrive_n(int id, int n) {
    asm volatile("bar.arrive %0, %1;" :: "r"(id), "r"(n) : "memory");
}

// Gate partial over ONE e-half: 2 gate rows (A=row p, B=row p+128), 8 batch elems.
template<int NK>
__device__ __forceinline__ void gate_half(const float* __restrict__ base, int eoff,
                                          const float* wA, const float* wB,
                                          u64 aA[4], u64 aB[4])
{
#pragma unroll
    for (int k = 0; k < NK; k++) {
        const ulonglong2* ptr = reinterpret_cast<const ulonglong2*>(base + k * ES + eoff);
        ulonglong2 q0 = ptr[0], q1 = ptr[1];
        u64 wa = splat2(wA[k]);
        u64 wb = splat2(wB[k]);
        ffma2(aA[0], q0.x, wa); ffma2(aB[0], q0.x, wb);
        ffma2(aA[1], q0.y, wa); ffma2(aB[1], q0.y, wb);
        ffma2(aA[2], q1.x, wa); ffma2(aB[2], q1.x, wb);
        ffma2(aA[3], q1.y, wa); ffma2(aB[3], q1.y, wb);
    }
}

__global__ void __launch_bounds__(NT, 1)
rnn_fused_kernel(const float* __restrict__ x,
                 const float* __restrict__ Wih0, const float* __restrict__ Whh0,
                 const float* __restrict__ bih0, const float* __restrict__ bhh0,
                 const float* __restrict__ Wih1, const float* __restrict__ Whh1,
                 const float* __restrict__ bih1, const float* __restrict__ bhh1,
                 const float* __restrict__ Wlin, const float* __restrict__ blin,
                 float* __restrict__ out)
{
    extern __shared__ float sm[];
    float* h1seq = sm + OFF_H1SEQ;
    float* zbuf  = sm + OFF_ZBUF;          // x rows [0,28) + h0 rows [28,92)
    float* hs    = sm + OFF_HS;            // 2 parity buffers
    ulonglong2* xch = reinterpret_cast<ulonglong2*>(sm + OFF_XCH); // 2 parity buffers
    float* actx  = sm + OFF_ACTX;
    float* wlin  = sm + OFF_WLIN;
    float* blin_s= sm + OFF_BLIN;

    const int tid = threadIdx.x;
    const int p   = tid & 127;             // row pair: rows (p, p+128)
    const int ks  = tid >> 7;              // K-half / owned e-half
    const int u   = p & 63;                // unit
    const bool ig = (p < 64);              // true: owns (i,g); false: (f,o)
    const int e0  = blockIdx.x * EE;
    const int fb  = 1 - ks;                // foreign e-half
    const int w   = tid >> 5;              // warp id
    const int idA = 1 + (w & 3);           // pairs (w, w+4): K-combine partners
    const int idB = 5 + (w & 1) + 2 * (w >> 2); // pairs (0,2),(1,3),(4,6),(5,7)

    // init
    for (int idx = tid; idx < K0 * ES; idx += NT) zbuf[idx] = 0.0f;
    for (int idx = tid; idx < 2 * HSZ; idx += NT) hs[idx] = 0.0f;
    for (int idx = tid; idx < OUTD * HID; idx += NT) wlin[idx] = Wlin[idx];
    if (tid < OUTD) blin_s[tid] = blin[tid];
    for (int i = tid; i < IND * EE; i += NT) {     // stage x(t=0)
        int e = i / IND, k = i % IND;
        zbuf[k * ES + e] = x[(size_t)(e0 + e) * (TT * IND) + k];
    }

    float c8[8];
#pragma unroll
    for (int q = 0; q < 8; q++) c8[q] = 0.0f;

    // ================= Layer 0 (full barriers — x staging is all-to-all) ====
    {
        float wA[K0H], wB[K0H];
#pragma unroll
        for (int i = 0; i < K0H; i++) {
            int cidx = ks * K0H + i;
            if (cidx < IND) {
                wA[i] = Wih0[p * IND + cidx];
                wB[i] = Wih0[(p + 128) * IND + cidx];
            } else {
                wA[i] = Whh0[p * HID + (cidx - IND)];
                wB[i] = Whh0[(p + 128) * HID + (cidx - IND)];
            }
        }
        const u64 biasA = splat2(bih0[p] + bhh0[p]);
        const u64 biasB = splat2(bih0[p + 128] + bhh0[p + 128]);
        const float* zbase = zbuf + ks * K0H * ES;

        __syncthreads();

#pragma unroll 1
        for (int t = 0; t < TT; t++) {
            // pass 1: foreign e-half, ship immediately (layer0: parity-0 buffer)
            {
                u64 fA[4] = {0ULL, 0ULL, 0ULL, 0ULL};
                u64 fB[4] = {0ULL, 0ULL, 0ULL, 0ULL};
                gate_half<K0H>(zbase, 8 * fb, wA, wB, fA, fB);
                xch[(fb * 4 + 0) * 128 + p] = make_ulonglong2(fA[0], fA[1]);
                xch[(fb * 4 + 1) * 128 + p] = make_ulonglong2(fA[2], fA[3]);
                xch[(fb * 4 + 2) * 128 + p] = make_ulonglong2(fB[0], fB[1]);
                xch[(fb * 4 + 3) * 128 + p] = make_ulonglong2(fB[2], fB[3]);
            }
            // pass 2: own e-half (bias pre-loaded)
            u64 oA[4] = {biasA, biasA, biasA, biasA};
            u64 oB[4] = {biasB, biasB, biasB, biasB};
            gate_half<K0H>(zbase, 8 * ks, wA, wB, oA, oB);
            bar_sync_n(idA, 64);

            {
                ulonglong2 v0 = xch[(ks * 4 + 0) * 128 + p];
                ulonglong2 v1 = xch[(ks * 4 + 1) * 128 + p];
                ulonglong2 v2 = xch[(ks * 4 + 2) * 128 + p];
                ulonglong2 v3 = xch[(ks * 4 + 3) * 128 + p];
                fadd2(oA[0], v0.x); fadd2(oA[1], v0.y); fadd2(oA[2], v1.x); fadd2(oA[3], v1.y);
                fadd2(oB[0], v2.x); fadd2(oB[1], v2.y); fadd2(oB[2], v3.x); fadd2(oB[3], v3.y);
            }

            float2 vA[4] = {unpack2(oA[0]), unpack2(oA[1]), unpack2(oA[2]), unpack2(oA[3])};
            float2 vB[4] = {unpack2(oB[0]), unpack2(oB[1]), unpack2(oB[2]), unpack2(oB[3])};

            float iv[8], gv[8];
            if (ig) {
#pragma unroll
                for (int q = 0; q < 4; q++) {
                    iv[2 * q] = sigfast(vA[q].x);  iv[2 * q + 1] = sigfast(vA[q].y);
                    gv[2 * q] = tanhfast(vB[q].x); gv[2 * q + 1] = tanhfast(vB[q].y);
                }
            } else {
                float* ab = actx + u * 36 + ks * 16;
                *reinterpret_cast<float4*>(ab)      = make_float4(sigfast(vA[0].x), sigfast(vA[0].y), sigfast(vA[1].x), sigfast(vA[1].y));
                *reinterpret_cast<float4*>(ab + 4)  = make_float4(sigfast(vA[2].x), sigfast(vA[2].y), sigfast(vA[3].x), sigfast(vA[3].y));
                *reinterpret_cast<float4*>(ab + 8)  = make_float4(sigfast(vB[0].x), sigfast(vB[0].y), sigfast(vB[1].x), sigfast(vB[1].y));
                *reinterpret_cast<float4*>(ab + 12) = make_float4(sigfast(vB[2].x), sigfast(vB[2].y), sigfast(vB[3].x), sigfast(vB[3].y));
            }
            __syncthreads();

            if (ig) {
                const float* ab = actx + u * 36 + ks * 16;
                float h[8];
#pragma unroll
                for (int q = 0; q < 8; q++) {
                    float fg = ab[q];
                    float og = ab[8 + q];
                    c8[q] = fg * c8[q] + iv[q] * gv[q];
                    h[q] = og * tanhfast(c8[q]);
                }
                float* d0 = zbuf + (IND + u) * ES + 8 * ks;
                float* d1 = h1seq + (t * HID + u) * ES + 8 * ks;
                float4 h0 = make_float4(h[0], h[1], h[2], h[3]);
                float4 h1 = make_float4(h[4], h[5], h[6], h[7]);
                *reinterpret_cast<float4*>(d0)     = h0;
                *reinterpret_cast<float4*>(d0 + 4) = h1;
                *reinterpret_cast<float4*>(d1)     = h0;
                *reinterpret_cast<float4*>(d1 + 4) = h1;
            } else if (t + 1 < TT) {
                int idx = (p - 64) + 64 * ks;
#pragma unroll
                for (int i2 = idx; i2 < IND * EE; i2 += 128) {
                    int e = i2 / IND, k = i2 % IND;
                    zbuf[k * ES + e] = x[(size_t)(e0 + e) * (TT * IND) + (t + 1) * IND + k];
                }
            }
            __syncthreads();
        }
    }

    // reset cell state for layer 1 (hs buffers already zeroed at init; h2(-1)=0 in buf 0)
#pragma unroll
    for (int q = 0; q < 8; q++) c8[q] = 0.0f;

    // ================= Layer 1 (relaxed barriers, parity buffers) ==========
    {
        // K=128: ks=0 -> Wih1 (operand h1seq[t], NON-recurrent); ks=1 -> Whh1 (operand hs)
        const float* Wsel = ks ? Whh1 : Wih1;
        float wA[K1H], wB[K1H];
#pragma unroll
        for (int i = 0; i < K1H; i++) {
            wA[i] = Wsel[p * HID + i];
            wB[i] = Wsel[(p + 128) * HID + i];
        }
        const u64 biasA = splat2(bih1[p] + bhh1[p]);
        const u64 biasB = splat2(bih1[p + 128] + bhh1[p + 128]);

        __syncthreads();

#pragma unroll 1
        for (int t = 0; t < TT; t++) {
            // parity views
            ulonglong2* xt = xch + (t & 1) * 1024;                // 8*128 entries
            const float* base = ks ? (hs + (t & 1) * HSZ)         // read h2(t-1)
                                   : (h1seq + t * HID * ES);

            {
                u64 fA[4] = {0ULL, 0ULL, 0ULL, 0ULL};
                u64 fB[4] = {0ULL, 0ULL, 0ULL, 0ULL};
                gate_half<K1H>(base, 8 * fb, wA, wB, fA, fB);
                xt[(fb * 4 + 0) * 128 + p] = make_ulonglong2(fA[0], fA[1]);
                xt[(fb * 4 + 1) * 128 + p] = make_ulonglong2(fA[2], fA[3]);
                xt[(fb * 4 + 2) * 128 + p] = make_ulonglong2(fB[0], fB[1]);
                xt[(fb * 4 + 3) * 128 + p] = make_ulonglong2(fB[2], fB[3]);
            }
            u64 oA[4] = {biasA, biasA, biasA, biasA};
            u64 oB[4] = {biasB, biasB, biasB, biasB};
            gate_half<K1H>(base, 8 * ks, wA, wB, oA, oB);
            bar_sync_n(idA, 64);           // partner (p, 1-ks) shipped my e-half

            {
                ulonglong2 v0 = xt[(ks * 4 + 0) * 128 + p];
                ulonglong2 v1 = xt[(ks * 4 + 1) * 128 + p];
                ulonglong2 v2 = xt[(ks * 4 + 2) * 128 + p];
                ulonglong2 v3 = xt[(ks * 4 + 3) * 128 + p];
                fadd2(oA[0], v0.x); fadd2(oA[1], v0.y); fadd2(oA[2], v1.x); fadd2(oA[3], v1.y);
                fadd2(oB[0], v2.x); fadd2(oB[1], v2.y); fadd2(oB[2], v3.x); fadd2(oB[3], v3.y);
            }

            float2 vA[4] = {unpack2(oA[0]), unpack2(oA[1]), unpack2(oA[2]), unpack2(oA[3])};
            float2 vB[4] = {unpack2(oB[0]), unpack2(oB[1]), unpack2(oB[2]), unpack2(oB[3])};

            if (ig) {
                float iv[8], gv[8];
#pragma unroll
                for (int q = 0; q < 4; q++) {
                    iv[2 * q] = sigfast(vA[q].x);  iv[2 * q + 1] = sigfast(vA[q].y);
                    gv[2 * q] = tanhfast(vB[q].x); gv[2 * q + 1] = tanhfast(vB[q].y);
                }
                bar_sync_n(idB, 64);       // wait for my fo partner's actx
                const float* ab = actx + u * 36 + ks * 16;
                float h[8];
#pragma unroll
                for (int q = 0; q < 8; q++) {
                    float fg = ab[q];
                    float og = ab[8 + q];
                    c8[q] = fg * c8[q] + iv[q] * gv[q];
                    h[q] = og * tanhfast(c8[q]);
                }
                // write h2(t) into the OTHER parity buffer
                float* d0 = hs + ((t + 1) & 1) * HSZ + u * ES + 8 * ks;
                *reinterpret_cast<float4*>(d0)     = make_float4(h[0], h[1], h[2], h[3]);
                *reinterpret_cast<float4*>(d0 + 4) = make_float4(h[4], h[5], h[6], h[7]);
            } else {
                float* ab = actx + u * 36 + ks * 16;
                *reinterpret_cast<float4*>(ab)      = make_float4(sigfast(vA[0].x), sigfast(vA[0].y), sigfast(vA[1].x), sigfast(vA[1].y));
                *reinterpret_cast<float4*>(ab + 4)  = make_float4(sigfast(vA[2].x), sigfast(vA[2].y), sigfast(vA[3].x), sigfast(vA[3].y));
                *reinterpret_cast<float4*>(ab + 8)  = make_float4(sigfast(vB[0].x), sigfast(vB[0].y), sigfast(vB[1].x), sigfast(vB[1].y));
                *reinterpret_cast<float4*>(ab + 12) = make_float4(sigfast(vB[2].x), sigfast(vB[2].y), sigfast(vB[3].x), sigfast(vB[3].y));
                bar_arrive_n(idB, 64);     // producer does not block
            }

            // End-of-t ordering for the h2 recurrence only:
            //   warps 4..7 read hs next iter  -> must SYNC
            //   warps 0,1 write hs but never read -> ARRIVE only
            //   warps 2,3 touch neither      -> free-run (skew <=1 via idA)
            if (w >= 4)      bar_sync_n(13, 192);
            else if (w < 2)  bar_arrive_n(13, 192);
        }
    }

    __syncthreads();   // rejoin all 8 warps before the head

    // ================= Linear head =================
    // h2(T-1) lives in parity buffer (TT & 1) == 0
    if (tid < OUTD * EE) {
        int e = tid & (EE - 1);
        int o = tid >> 4;
        float s = blin_s[o];
        const float* hlast = hs + (TT & 1) * HSZ;
#pragma unroll
        for (int k = 0; k < HID; k++)
            s += wlin[o * HID + k] * hlast[k * ES + e];
        out[(size_t)(e0 + e) * OUTD + o] = s;
    }
}

extern "C" void kernel_launch(void* const* d_in, const int* in_sizes, int n_in,
                              void* d_out, int out_size)
{
    const float* x    = (const float*)d_in[0];
    const float* Wih0 = (const float*)d_in[1];
    const float* Whh0 = (const float*)d_in[2];
    const float* bih0 = (const float*)d_in[3];
    const float* bhh0 = (const float*)d_in[4];
    const float* Wih1 = (const float*)d_in[5];
    const float* Whh1 = (const float*)d_in[6];
    const float* bih1 = (const float*)d_in[7];
    const float* bhh1 = (const float*)d_in[8];
    const float* Wlin = (const float*)d_in[9];
    const float* blin = (const float*)d_in[10];
    float* out = (float*)d_out;

    int B = in_sizes[0] / (TT * IND);   // 16384
    int grid = B / EE;                  // 1024

    cudaFuncSetAttribute(rnn_fused_kernel,
                         cudaFuncAttributeMaxDynamicSharedMemorySize, SMEM_BYTES);
    rnn_fused_kernel<<<grid, NT, SMEM_BYTES>>>(
        x, Wih0, Whh0, bih0, bhh0, Wih1, Whh1, bih1, bhh1, Wlin, blin, out);
}

// round 15
// speedup vs baseline: 1.2619x; 1.2619x over previous
#include <cuda_runtime.h>
#include <cuda_bf16.h>
#include <cstdint>

#define TT   28
#define IND  28
#define HID  64
#define OUTD 10
#define BT   64
#define NT   256
#define NB   16384
#define WSTR 272                    // weight staging row stride (bytes)
#define WS_LO (256*WSTR)
#define SMEM_BYTES (2*256*WSTR)     // 139264

__device__ uint32_t g_h1[(size_t)TT * HID * NB];   // h1 as packed (hi,lo) bf16

typedef unsigned short u16;
typedef uint32_t u32;

__device__ __forceinline__ float tanhfast(float v){
    float r; asm("tanh.approx.f32 %0, %1;" : "=f"(r) : "f"(v)); return r;
}
__device__ __forceinline__ float sigfast(float v){
    return fmaf(0.5f, tanhfast(0.5f*v), 0.5f);
}
__device__ __forceinline__ void splitbf(float v, u16& h, u16& l){
    __nv_bfloat16 hb = __float2bfloat16(v);
    float hf = __bfloat162float(hb);
    __nv_bfloat16 lb = __float2bfloat16(v - hf);
    h = __bfloat16_as_ushort(hb);
    l = __bfloat16_as_ushort(lb);
}
__device__ __forceinline__ void mma16816(float* d, const u32* a, u32 b0, u32 b1){
    asm volatile(
        "mma.sync.aligned.m16n8k16.row.col.f32.bf16.bf16.f32 "
        "{%0,%1,%2,%3}, {%4,%5,%6,%7}, {%8,%9}, {%0,%1,%2,%3};"
        : "+f"(d[0]), "+f"(d[1]), "+f"(d[2]), "+f"(d[3])
        : "r"(a[0]), "r"(a[1]), "r"(a[2]), "r"(a[3]), "r"(b0), "r"(b1));
}

// Stage inputs of timestep t into parity block (t&1) of Z.
template<int ZSTR, bool L0, int AIN>
__device__ __forceinline__ void stage_in(char* smp, const float* x, int e0, int t, int tid)
{
    const int ZPART = 64 * ZSTR;
    const int pi = t & 1;
    if constexpr (L0) {
        for (int i = tid; i < 64 * IND; i += NT) {
            int b = i / IND, k = i - b * IND;
            float v = x[(size_t)(e0 + b) * (TT * IND) + t * IND + k];
            u16 hh, ll; splitbf(v, hh, ll);
            int off = b * ZSTR + 2 * (AIN * pi + k);
            *(u16*)(smp + off) = hh;
            *(u16*)(smp + ZPART + off) = ll;
        }
    } else {
        const int u = tid >> 2, b0 = (tid & 3) * 16;
        const u32* src = g_h1 + ((size_t)t * HID + u) * NB + e0 + b0;
#pragma unroll
        for (int c4 = 0; c4 < 4; c4++) {
            uint4 pk = *(const uint4*)(src + 4 * c4);
            u32 vals[4] = {pk.x, pk.y, pk.z, pk.w};
#pragma unroll
            for (int r = 0; r < 4; r++) {
                int b = b0 + 4 * c4 + r;
                int off = b * ZSTR + 2 * (AIN * pi + u);
                *(u16*)(smp + off) = (u16)(vals[r] & 0xffffu);
                *(u16*)(smp + ZPART + off) = (u16)(vals[r] >> 16);
            }
        }
    }
}

// One LSTM layer with mma.sync. Gate rows permuted rp = 4u+gate.
// Z batch-major: row b (64), cols: 2 parity input blocks of AIN, then
// 2 parity h blocks of 64 at HBASE=2*AIN. hi part at 0, lo at ZPART.
template<int KT, int KIN, int AIN, int ZSTR, bool L0>
__device__ __forceinline__ void run_layer(
    char* __restrict__ smp,
    const float* __restrict__ Wih, const float* __restrict__ Whh,
    const float* __restrict__ bih, const float* __restrict__ bhh,
    const float* __restrict__ x, int e0)
{
    constexpr int ZPART  = 64 * ZSTR;
    constexpr int HBASE  = 2 * AIN;
    constexpr int ITILES = AIN / 16;

    const int tid = threadIdx.x;
    const int w   = tid >> 5;
    const int L   = tid & 31;
    const int q   = L >> 2;            // fragment row group
    const int a   = L & 3;             // fragment col-pair
    const int g   = q & 3;             // lane's gate type
    const int qq  = q >> 2;

    // ---- stage split weights (permuted rows, logical K layout) ----
    for (int idx = tid; idx < 256 * 128; idx += NT) {
        int rp = idx >> 7, k = idx & 127;
        int orow = (rp & 3) * 64 + (rp >> 2);
        float v = 0.0f;
        if (k < AIN) { if (k < KIN) v = Wih[orow * KIN + k]; }
        else if (k < AIN + 64) v = Whh[orow * 64 + (k - AIN)];
        u16 hh, ll; splitbf(v, hh, ll);
        *(u16*)(smp + rp * WSTR + 2 * k) = hh;
        *(u16*)(smp + WS_LO + rp * WSTR + 2 * k) = ll;
    }
    __syncthreads();

    // ---- load A fragments (held for the whole layer) ----
    u32 Ahi[2][KT][4], Alo[2][KT][4];
#pragma unroll
    for (int mi = 0; mi < 2; mi++) {
        const int mt = 2 * w + mi;
        const int rlo = (16 * mt + q) * WSTR;
        const int rhi = rlo + 8 * WSTR;
#pragma unroll
        for (int kt = 0; kt < KT; kt++) {
            const int o0 = 32 * kt + 4 * a;
            Ahi[mi][kt][0] = *(const u32*)(smp + rlo + o0);
            Ahi[mi][kt][1] = *(const u32*)(smp + rhi + o0);
            Ahi[mi][kt][2] = *(const u32*)(smp + rlo + o0 + 16);
            Ahi[mi][kt][3] = *(const u32*)(smp + rhi + o0 + 16);
            Alo[mi][kt][0] = *(const u32*)(smp + WS_LO + rlo + o0);
            Alo[mi][kt][1] = *(const u32*)(smp + WS_LO + rhi + o0);
            Alo[mi][kt][2] = *(const u32*)(smp + WS_LO + rlo + o0 + 16);
            Alo[mi][kt][3] = *(const u32*)(smp + WS_LO + rhi + o0 + 16);
        }
    }
    float bias[2][2];
#pragma unroll
    for (int mi = 0; mi < 2; mi++) {
        int ul = 4 * (2 * w + mi) + qq;
        bias[mi][0] = bih[g * 64 + ul] + bhh[g * 64 + ul];
        bias[mi][1] = bih[g * 64 + ul + 2] + bhh[g * 64 + ul + 2];
    }
    __syncthreads();                 // frags loaded; smem now reusable as Z

    // ---- zero Z (h(-1)=0 + pad cols), stage t=0 ----
    for (int idx = tid; idx < 2 * ZPART / 4; idx += NT)
        ((u32*)smp)[idx] = 0;
    __syncthreads();
    stage_in<ZSTR, L0, AIN>(smp, x, e0, 0, tid);
    __syncthreads();

    float c16[2][2][4];
#pragma unroll
    for (int i = 0; i < 2; i++)
#pragma unroll
        for (int jx = 0; jx < 2; jx++)
#pragma unroll
            for (int j = 0; j < 4; j++) c16[i][jx][j] = 0.0f;

#pragma unroll 1
    for (int t = 0; t < TT; t++) {
        const int pi    = t & 1;
        const int ph_rd = (t + 1) & 1;     // h(t-1) block
        const int ph_wr = t & 1;           // h(t) block

        float acc[2][8][4];
#pragma unroll
        for (int mi = 0; mi < 2; mi++)
#pragma unroll
            for (int nt = 0; nt < 8; nt++) {
                acc[mi][nt][0] = bias[mi][0]; acc[mi][nt][1] = bias[mi][0];
                acc[mi][nt][2] = bias[mi][1]; acc[mi][nt][3] = bias[mi][1];
            }

#pragma unroll
        for (int kt = 0; kt < KT; kt++) {
            const int cb = (kt < ITILES) ? (AIN * pi + 16 * kt)
                                         : (HBASE + 64 * ph_rd + 16 * (kt - ITILES));
#pragma unroll
            for (int nt = 0; nt < 8; nt++) {
                const char* zb = smp + (8 * nt + q) * ZSTR + 2 * (cb + 2 * a);
                u32 bh0 = *(const u32*)(zb);
                u32 bh1 = *(const u32*)(zb + 16);
                u32 bl0 = *(const u32*)(zb + ZPART);
                u32 bl1 = *(const u32*)(zb + ZPART + 16);
#pragma unroll
                for (int mi = 0; mi < 2; mi++) {
                    mma16816(acc[mi][nt], Ahi[mi][kt], bh0, bh1);
                    mma16816(acc[mi][nt], Ahi[mi][kt], bl0, bl1);
                    mma16816(acc[mi][nt], Alo[mi][kt], bh0, bh1);
                }
            }
        }

        // ---- epilogue: activate, shfl gate exchange, cell update, emit h ----
#pragma unroll
        for (int mi = 0; mi < 2; mi++) {
#pragma unroll
            for (int nt = 0; nt < 8; nt++) {
                float av[4], s1[4], s2[4], s3[4];
#pragma unroll
                for (int j = 0; j < 4; j++) {
                    float v = acc[mi][nt][j];
                    av[j] = (g == 2) ? tanhfast(v) : sigfast(v);
                }
#pragma unroll
                for (int j = 0; j < 4; j++) {
                    s1[j] = __shfl_xor_sync(0xffffffffu, av[j], 4);
                    s2[j] = __shfl_xor_sync(0xffffffffu, av[j], 8);
                    s3[j] = __shfl_xor_sync(0xffffffffu, av[j], 12);
                }
                if ((nt & 3) == g) {           // lane owns n-tiles {g, g+4}
                    const int sel = nt >> 2;
                    const int bb0 = 8 * nt + 2 * a;
#pragma unroll
                    for (int j = 0; j < 4; j++) {
                        float vi = (g==0)?av[j]:(g==1)?s1[j]:(g==2)?s2[j]:s3[j];
                        float vf = (g==1)?av[j]:(g==0)?s1[j]:(g==3)?s2[j]:s3[j];
                        float vg = (g==2)?av[j]:(g==3)?s1[j]:(g==0)?s2[j]:s3[j];
                        float vo = (g==3)?av[j]:(g==2)?s1[j]:(g==1)?s2[j]:s3[j];
                        float cc = fmaf(vf, c16[mi][sel][j], vi * vg);
                        c16[mi][sel][j] = cc;
                        float h = vo * tanhfast(cc);
                        const int uu = 4 * (2 * w + mi) + qq + 2 * (j >> 1);
                        const int b  = bb0 + (j & 1);
                        u16 hh, ll; splitbf(h, hh, ll);
                        const int off = b * ZSTR + 2 * (HBASE + 64 * ph_wr + uu);
                        *(u16*)(smp + off) = hh;
                        *(u16*)(smp + ZPART + off) = ll;
                        if constexpr (L0)
                            g_h1[((size_t)t * HID + uu) * NB + e0 + b] =
                                (u32)hh | ((u32)ll << 16);
                    }
                }
            }
        }

        if (t + 1 < TT) stage_in<ZSTR, L0, AIN>(smp, x, e0, t + 1, tid);
        __syncthreads();
    }
}

__global__ void __launch_bounds__(NT, 1)
rnn_mma_kernel(const float* __restrict__ x,
               const float* __restrict__ Wih0, const float* __restrict__ Whh0,
               const float* __restrict__ bih0, const float* __restrict__ bhh0,
               const float* __restrict__ Wih1, const float* __restrict__ Whh1,
               const float* __restrict__ bih1, const float* __restrict__ bhh1,
               const float* __restrict__ Wlin, const float* __restrict__ blin,
               float* __restrict__ out)
{
    extern __shared__ char smp[];
    const int tid = threadIdx.x;
    const int e0 = blockIdx.x * BT;

    run_layer<6, 28, 32, 400, true >(smp, Wih0, Whh0, bih0, bhh0, x, e0);
    __syncthreads();
    run_layer<8, 64, 64, 528, false>(smp, Wih1, Whh1, bih1, bhh1, nullptr, e0);
    // layer1 loop ends with __syncthreads(): h2(TT-1) visible to all

    // ---- linear head: h2(TT-1) in Z h-block parity (TT-1)&1 = 1 ----
    constexpr int ZSTR1  = 528;
    constexpr int ZPART1 = 64 * ZSTR1;
    constexpr int HCOL   = 128 + 64 * ((TT - 1) & 1);
    for (int i = tid; i < BT * OUTD; i += NT) {
        int b = i / OUTD, o = i - b * OUTD;
        float s = blin[o];
#pragma unroll
        for (int u = 0; u < HID; u++) {
            int off = b * ZSTR1 + 2 * (HCOL + u);
            float h = __bfloat162float(__ushort_as_bfloat16(*(u16*)(smp + off))) +
                      __bfloat162float(__ushort_as_bfloat16(*(u16*)(smp + ZPART1 + off)));
            s += Wlin[o * HID + u] * h;
        }
        out[(size_t)(e0 + b) * OUTD + o] = s;
    }
}

extern "C" void kernel_launch(void* const* d_in, const int* in_sizes, int n_in,
                              void* d_out, int out_size)
{
    const float* x    = (const float*)d_in[0];
    const float* Wih0 = (const float*)d_in[1];
    const float* Whh0 = (const float*)d_in[2];
    const float* bih0 = (const float*)d_in[3];
    const float* bhh0 = (const float*)d_in[4];
    const float* Wih1 = (const float*)d_in[5];
    const float* Whh1 = (const float*)d_in[6];
    const float* bih1 = (const float*)d_in[7];
    const float* bhh1 = (const float*)d_in[8];
    const float* Wlin = (const float*)d_in[9];
    const float* blin = (const float*)d_in[10];
    float* out = (float*)d_out;

    int B = in_sizes[0] / (TT * IND);   // 16384
    int grid = B / BT;                  // 256

    cudaFuncSetAttribute(rnn_mma_kernel,
                         cudaFuncAttributeMaxDynamicSharedMemorySize, SMEM_BYTES);
    rnn_mma_kernel<<<grid, NT, SMEM_BYTES>>>(
        x, Wih0, Whh0, bih0, bhh0, Wih1, Whh1, bih1, bhh1, Wlin, blin, out);
}

// round 16
// speedup vs baseline: 2.0142x; 1.5962x over previous
#include <cuda_runtime.h>
#include <cuda_bf16.h>
#include <cstdint>

#define TT   28
#define IND  28
#define HID  64
#define OUTD 10
#define BT   128
#define NT   512
#define NB   16384
#define WSTR 272                    // weight staging row stride (bytes)
#define WS_LO (256*WSTR)
#define SMEM_BYTES (2*256*WSTR)     // 139264 (covers Z: 2*128*528=135168)

__device__ uint32_t g_h1[(size_t)TT * HID * NB];   // h1 as packed (hi,lo) bf16

typedef unsigned short u16;
typedef uint32_t u32;

__device__ __forceinline__ float tanhfast(float v){
    float r; asm("tanh.approx.f32 %0, %1;" : "=f"(r) : "f"(v)); return r;
}
__device__ __forceinline__ float sigfast(float v){
    return fmaf(0.5f, tanhfast(0.5f*v), 0.5f);
}
__device__ __forceinline__ void splitbf(float v, u16& h, u16& l){
    __nv_bfloat16 hb = __float2bfloat16(v);
    float hf = __bfloat162float(hb);
    __nv_bfloat16 lb = __float2bfloat16(v - hf);
    h = __bfloat16_as_ushort(hb);
    l = __bfloat16_as_ushort(lb);
}
__device__ __forceinline__ void mma16816(float* d, const u32* a, u32 b0, u32 b1){
    asm volatile(
        "mma.sync.aligned.m16n8k16.row.col.f32.bf16.bf16.f32 "
        "{%0,%1,%2,%3}, {%4,%5,%6,%7}, {%8,%9}, {%0,%1,%2,%3};"
        : "+f"(d[0]), "+f"(d[1]), "+f"(d[2]), "+f"(d[3])
        : "r"(a[0]), "r"(a[1]), "r"(a[2]), "r"(a[3]), "r"(b0), "r"(b1));
}

// Stage inputs of timestep t into parity block (t&1) of Z.
template<int ZSTR, bool L0, int AIN>
__device__ __forceinline__ void stage_in(char* smp, const float* x, int e0, int t, int tid)
{
    const int ZPART = BT * ZSTR;
    const int pi = t & 1;
    if constexpr (L0) {
        for (int i = tid; i < BT * IND; i += NT) {
            int b = i / IND, k = i - b * IND;
            float v = x[(size_t)(e0 + b) * (TT * IND) + t * IND + k];
            u16 hh, ll; splitbf(v, hh, ll);
            int off = b * ZSTR + 2 * (AIN * pi + k);
            *(u16*)(smp + off) = hh;
            *(u16*)(smp + ZPART + off) = ll;
        }
    } else {
        const int u = tid >> 3, b0 = (tid & 7) * 16;
        const u32* src = g_h1 + ((size_t)t * HID + u) * NB + e0 + b0;
#pragma unroll
        for (int c4 = 0; c4 < 4; c4++) {
            uint4 pk = *(const uint4*)(src + 4 * c4);
            u32 vals[4] = {pk.x, pk.y, pk.z, pk.w};
#pragma unroll
            for (int r = 0; r < 4; r++) {
                int b = b0 + 4 * c4 + r;
                int off = b * ZSTR + 2 * (AIN * pi + u);
                *(u16*)(smp + off) = (u16)(vals[r] & 0xffffu);
                *(u16*)(smp + ZPART + off) = (u16)(vals[r] >> 16);
            }
        }
    }
}

// One LSTM layer with mma.sync, 16 warps (1 m-tile each), BT=128.
// Gate-pair row permutation: staged row rp = 16*mt + d with
//   unit = 4*mt + ((d&7)>>1), gate = 2*(d&1) + (d>>3)
// so lane q holds gates {2h, 2h+1} (h=q&1) of unit 4*mt+(q>>1), and its
// xor-4 partner holds the other two gates of the SAME unit.
template<int KT, int KIN, int AIN, int ZSTR, bool L0>
__device__ __forceinline__ void run_layer(
    char* __restrict__ smp,
    const float* __restrict__ Wih, const float* __restrict__ Whh,
    const float* __restrict__ bih, const float* __restrict__ bhh,
    const float* __restrict__ x, int e0)
{
    constexpr int ZPART  = BT * ZSTR;
    constexpr int HBASE  = 2 * AIN;
    constexpr int ITILES = AIN / 16;

    const int tid = threadIdx.x;
    const int w   = tid >> 5;          // warp = m-tile (16)
    const int L   = tid & 31;
    const int q   = L >> 2;            // fragment row group
    const int a   = L & 3;             // fragment col-pair
    const int half = q & 1;            // gate half: 0 -> {i,f}, 1 -> {g,o}
    const int u    = 4 * w + (q >> 1); // this lane's unit

    // ---- stage split weights (gate-pair permuted rows) ----
    for (int idx = tid; idx < 256 * 128; idx += NT) {
        int rp = idx >> 7, k = idx & 127;
        int d = rp & 15;
        int orow = (2 * (d & 1) + (d >> 3)) * 64 + (4 * (rp >> 4) + ((d & 7) >> 1));
        float v = 0.0f;
        if (k < AIN) { if (k < KIN) v = Wih[orow * KIN + k]; }
        else if (k < AIN + 64) v = Whh[orow * 64 + (k - AIN)];
        u16 hh, ll; splitbf(v, hh, ll);
        *(u16*)(smp + rp * WSTR + 2 * k) = hh;
        *(u16*)(smp + WS_LO + rp * WSTR + 2 * k) = ll;
    }
    __syncthreads();

    // ---- load A fragments (held for the whole layer) ----
    u32 Ahi[KT][4], Alo[KT][4];
    {
        const int rlo = (16 * w + q) * WSTR;
        const int rhi = rlo + 8 * WSTR;
#pragma unroll
        for (int kt = 0; kt < KT; kt++) {
            const int o0 = 32 * kt + 4 * a;
            Ahi[kt][0] = *(const u32*)(smp + rlo + o0);
            Ahi[kt][1] = *(const u32*)(smp + rhi + o0);
            Ahi[kt][2] = *(const u32*)(smp + rlo + o0 + 16);
            Ahi[kt][3] = *(const u32*)(smp + rhi + o0 + 16);
            Alo[kt][0] = *(const u32*)(smp + WS_LO + rlo + o0);
            Alo[kt][1] = *(const u32*)(smp + WS_LO + rhi + o0);
            Alo[kt][2] = *(const u32*)(smp + WS_LO + rlo + o0 + 16);
            Alo[kt][3] = *(const u32*)(smp + WS_LO + rhi + o0 + 16);
        }
    }
    const float bias0 = bih[(2 * half) * 64 + u] + bhh[(2 * half) * 64 + u];
    const float bias1 = bih[(2 * half + 1) * 64 + u] + bhh[(2 * half + 1) * 64 + u];
    __syncthreads();                 // frags loaded; smem reusable as Z

    // ---- zero Z (h(-1)=0 + pads), stage t=0 ----
    for (int idx = tid; idx < 2 * ZPART / 4; idx += NT)
        ((u32*)smp)[idx] = 0;
    __syncthreads();
    stage_in<ZSTR, L0, AIN>(smp, x, e0, 0, tid);
    __syncthreads();

    float c16[16];
#pragma unroll
    for (int i = 0; i < 16; i++) c16[i] = 0.0f;

#pragma unroll 1
    for (int t = 0; t < TT; t++) {
        const int pi    = t & 1;
        const int ph_rd = (t + 1) & 1;
        const int ph_wr = t & 1;

#pragma unroll
        for (int chunk = 0; chunk < 4; chunk++) {
            float acc[4][4];
#pragma unroll
            for (int ntl = 0; ntl < 4; ntl++) {
                acc[ntl][0] = bias0; acc[ntl][1] = bias0;
                acc[ntl][2] = bias1; acc[ntl][3] = bias1;
            }

#pragma unroll
            for (int kt = 0; kt < KT; kt++) {
                const int cb = (kt < ITILES) ? (AIN * pi + 16 * kt)
                                             : (HBASE + 64 * ph_rd + 16 * (kt - ITILES));
#pragma unroll
                for (int ntl = 0; ntl < 4; ntl++) {
                    const int nt = chunk * 4 + ntl;
                    const char* zb = smp + (8 * nt + q) * ZSTR + 2 * (cb + 2 * a);
                    u32 bh0 = *(const u32*)(zb);
                    u32 bh1 = *(const u32*)(zb + 16);
                    u32 bl0 = *(const u32*)(zb + ZPART);
                    u32 bl1 = *(const u32*)(zb + ZPART + 16);
                    mma16816(acc[ntl], Ahi[kt], bh0, bh1);
                    mma16816(acc[ntl], Ahi[kt], bl0, bl1);
                    mma16816(acc[ntl], Alo[kt], bh0, bh1);
                }
            }

            // ---- epilogue for this chunk ----
#pragma unroll
            for (int ntl = 0; ntl < 4; ntl++) {
                const int nt = chunk * 4 + ntl;
                float av[4];
                if (half == 0) {          // gates i (j=0,1), f (j=2,3)
                    av[0] = sigfast(acc[ntl][0]); av[1] = sigfast(acc[ntl][1]);
                    av[2] = sigfast(acc[ntl][2]); av[3] = sigfast(acc[ntl][3]);
                } else {                  // gates g (j=0,1), o (j=2,3)
                    av[0] = tanhfast(acc[ntl][0]); av[1] = tanhfast(acc[ntl][1]);
                    av[2] = sigfast(acc[ntl][2]);  av[3] = sigfast(acc[ntl][3]);
                }
                float pv[4];
#pragma unroll
                for (int j = 0; j < 4; j++)
                    pv[j] = __shfl_xor_sync(0xffffffffu, av[j], 4);

                // this lane updates column b = 8nt + 2a + half
                const int jc = half;
                float vi, vf, vg, vo;
                if (half == 0) { vi = av[jc]; vf = av[2 + jc]; vg = pv[jc]; vo = pv[2 + jc]; }
                else           { vg = av[jc]; vo = av[2 + jc]; vi = pv[jc]; vf = pv[2 + jc]; }

                float cc = fmaf(vf, c16[nt], vi * vg);
                c16[nt] = cc;
                float h = vo * tanhfast(cc);
                const int b = 8 * nt + 2 * a + half;
                u16 hh, ll; splitbf(h, hh, ll);
                const int off = b * ZSTR + 2 * (HBASE + 64 * ph_wr + u);
                *(u16*)(smp + off) = hh;
                *(u16*)(smp + ZPART + off) = ll;
                if constexpr (L0)
                    g_h1[((size_t)t * HID + u) * NB + e0 + b] =
                        (u32)hh | ((u32)ll << 16);
            }
        }

        if (t + 1 < TT) stage_in<ZSTR, L0, AIN>(smp, x, e0, t + 1, tid);
        __syncthreads();
    }
}

__global__ void __launch_bounds__(NT, 1)
rnn_mma_kernel(const float* __restrict__ x,
               const float* __restrict__ Wih0, const float* __restrict__ Whh0,
               const float* __restrict__ bih0, const float* __restrict__ bhh0,
               const float* __restrict__ Wih1, const float* __restrict__ Whh1,
               const float* __restrict__ bih1, const float* __restrict__ bhh1,
               const float* __restrict__ Wlin, const float* __restrict__ blin,
               float* __restrict__ out)
{
    extern __shared__ char smp[];
    const int tid = threadIdx.x;
    const int e0 = blockIdx.x * BT;

    run_layer<6, 28, 32, 400, true >(smp, Wih0, Whh0, bih0, bhh0, x, e0);
    __syncthreads();
    run_layer<8, 64, 64, 528, false>(smp, Wih1, Whh1, bih1, bhh1, nullptr, e0);
    // layer1 loop ends with __syncthreads(): h2(TT-1) visible to all

    // ---- linear head: h2(TT-1) in Z h-block parity (TT-1)&1 = 1 ----
    constexpr int ZSTR1  = 528;
    constexpr int ZPART1 = BT * ZSTR1;
    constexpr int HCOL   = 128 + 64 * ((TT - 1) & 1);
    for (int i = tid; i < BT * OUTD; i += NT) {
        int b = i / OUTD, o = i - b * OUTD;
        float s = blin[o];
#pragma unroll
        for (int u = 0; u < HID; u++) {
            int off = b * ZSTR1 + 2 * (HCOL + u);
            float h = __bfloat162float(__ushort_as_bfloat16(*(u16*)(smp + off))) +
                      __bfloat162float(__ushort_as_bfloat16(*(u16*)(smp + ZPART1 + off)));
            s += Wlin[o * HID + u] * h;
        }
        out[(size_t)(e0 + b) * OUTD + o] = s;
    }
}

extern "C" void kernel_launch(void* const* d_in, const int* in_sizes, int n_in,
                              void* d_out, int out_size)
{
    const float* x    = (const float*)d_in[0];
    const float* Wih0 = (const float*)d_in[1];
    const float* Whh0 = (const float*)d_in[2];
    const float* bih0 = (const float*)d_in[3];
    const float* bhh0 = (const float*)d_in[4];
    const float* Wih1 = (const float*)d_in[5];
    const float* Whh1 = (const float*)d_in[6];
    const float* bih1 = (const float*)d_in[7];
    const float* bhh1 = (const float*)d_in[8];
    const float* Wlin = (const float*)d_in[9];
    const float* blin = (const float*)d_in[10];
    float* out = (float*)d_out;

    int B = in_sizes[0] / (TT * IND);   // 16384
    int grid = B / BT;                  // 128

    cudaFuncSetAttribute(rnn_mma_kernel,
                         cudaFuncAttributeMaxDynamicSharedMemorySize, SMEM_BYTES);
    rnn_mma_kernel<<<grid, NT, SMEM_BYTES>>>(
        x, Wih0, Whh0, bih0, bhh0, Wih1, Whh1, bih1, bhh1, Wlin, blin, out);
}